// round 2
// baseline (speedup 1.0000x reference)
#include <cuda_runtime.h>
#include <cstdint>

// ---------------------------------------------------------------------------
// GridCell: B=64, T=512, D_IN=1024, D_HID=1024, D_G=512
//   x0 = latents[:,0]
//   h  = relu(x0@W1^T+b1); h = relu(h@W2^T+b2); g0 = norm_relu(h@W3^T+b3)
//   vel = latents[:,1:]-latents[:,:-1];  vin[t,b,g] = sum_d vel[b,t,d]*W_in[g,d]
//   g_t = norm_relu(g_{t-1}@W_rec^T + vin[t-1])   (t=1..511)
//   out[b,t,:] = g_t
// ---------------------------------------------------------------------------

namespace {
constexpr int B_   = 64;
constexpr int T_   = 512;
constexpr int DIN  = 1024;
constexpr int DHID = 1024;
constexpr int DG   = 512;
constexpr int TV   = T_ - 1;        // 511
constexpr int MV   = TV * B_;       // 32704 rows in the vin GEMM
constexpr float EPS_ = 1e-6f;
}

// Scratch (static device allocations are the sanctioned scratch mechanism)
__device__ float g_vin[(size_t)MV * DG];   // [t][b][g]
__device__ float g_h1[B_ * DHID];
__device__ float g_h2[B_ * DG];
__device__ float g_g0[B_ * DG];            // relu'd, pre-normalization
__device__ int   g_notI;

// ---------------------------------------------------------------------------
__global__ void reset_flag_k() { g_notI = 0; }

__global__ void check_id_k(const float* __restrict__ Wr) {
    int i = blockIdx.x * blockDim.x + threadIdx.x;
    if (i >= DG * DG) return;
    int r = i >> 9;
    int c = i & (DG - 1);
    float e = (r == c) ? 1.0f : 0.0f;
    if (Wr[i] != e) g_notI = 1;   // benign race: all writers store 1
}

// ---------------------------------------------------------------------------
// Small MLP GEMM: C = relu(A @ W^T + bias), M = 64 exactly.
// BM=BN=64, BK=16, 256 threads, 4x4 per thread.
// stage: 0 -> A=Ain(latents row-0, lda given), C=g_h1
//        1 -> A=g_h1, C=g_h2
//        2 -> A=g_h2, C=g_g0
__global__ void mlp_gemm_k(const float* __restrict__ Ain, int lda,
                           const float* __restrict__ W,
                           const float* __restrict__ bias,
                           int stage, int N, int K) {
    __shared__ float As[16][64];
    __shared__ float Bs[16][64];

    const float* A = (stage == 0) ? Ain : (stage == 1 ? g_h1 : g_h2);
    float*       C = (stage == 0) ? g_h1 : (stage == 1 ? g_h2 : g_g0);

    const int tid  = threadIdx.x;
    const int bn   = blockIdx.x * 64;
    const int lrow = tid >> 2;          // 0..63
    const int lcol = (tid & 3) << 2;    // 0,4,8,12
    const int tx   = tid & 15;          // col group
    const int ty   = tid >> 4;          // row group

    float acc[4][4];
    #pragma unroll
    for (int i = 0; i < 4; i++)
        #pragma unroll
        for (int j = 0; j < 4; j++) acc[i][j] = 0.0f;

    for (int k0 = 0; k0 < K; k0 += 16) {
        float4 a4 = *(const float4*)(A + (size_t)lrow * lda + k0 + lcol);
        float4 b4 = *(const float4*)(W + (size_t)(bn + lrow) * K + k0 + lcol);
        As[lcol + 0][lrow] = a4.x; As[lcol + 1][lrow] = a4.y;
        As[lcol + 2][lrow] = a4.z; As[lcol + 3][lrow] = a4.w;
        Bs[lcol + 0][lrow] = b4.x; Bs[lcol + 1][lrow] = b4.y;
        Bs[lcol + 2][lrow] = b4.z; Bs[lcol + 3][lrow] = b4.w;
        __syncthreads();
        #pragma unroll
        for (int kk = 0; kk < 16; kk++) {
            float4 av = *(const float4*)&As[kk][ty * 4];
            float4 bv = *(const float4*)&Bs[kk][tx * 4];
            float a[4] = {av.x, av.y, av.z, av.w};
            float b[4] = {bv.x, bv.y, bv.z, bv.w};
            #pragma unroll
            for (int i = 0; i < 4; i++)
                #pragma unroll
                for (int j = 0; j < 4; j++) acc[i][j] += a[i] * b[j];
        }
        __syncthreads();
    }

    #pragma unroll
    for (int i = 0; i < 4; i++) {
        int m = ty * 4 + i;
        #pragma unroll
        for (int j = 0; j < 4; j++) {
            int n = bn + tx * 4 + j;
            float v = acc[i][j] + bias[n];
            C[(size_t)m * N + n] = fmaxf(v, 0.0f);
        }
    }
}

// ---------------------------------------------------------------------------
// vin GEMM: g_vin[m, n] = sum_k (L[b,t+1,k]-L[b,t,k]) * Win[n,k],  m = t*64+b
// BM=BN=128, BK=8, 256 threads, 8x8 per thread, reg-prefetch of next K-slice.
__global__ void vin_gemm_k(const float* __restrict__ L,
                           const float* __restrict__ Win) {
    __shared__ float As[8][128];
    __shared__ float Bs[8][128];

    const int tid  = threadIdx.x;
    const int bm   = blockIdx.y * 128;
    const int bn   = blockIdx.x * 128;
    const int arow = tid >> 1;          // 0..127
    const int acol = (tid & 1) << 2;    // 0 or 4
    const int tx   = tid & 15;          // n0 = tx*8
    const int ty   = tid >> 4;          // m0 = ty*8

    const int m = bm + arow;
    const bool mval = (m < MV);
    const float* p0 = L;
    const float* p1 = L;
    if (mval) {
        int t  = m >> 6;
        int bb = m & 63;
        size_t base = ((size_t)bb * T_ + t) * DIN;
        p0 = L + base;
        p1 = L + base + DIN;
    }
    const float* wp = Win + (size_t)(bn + arow) * DIN;

    float acc[8][8];
    #pragma unroll
    for (int i = 0; i < 8; i++)
        #pragma unroll
        for (int j = 0; j < 8; j++) acc[i][j] = 0.0f;

    // prologue load (k0 = 0)
    float4 av = make_float4(0.f, 0.f, 0.f, 0.f);
    float4 bv;
    if (mval) {
        float4 x1 = *(const float4*)(p1 + acol);
        float4 x0 = *(const float4*)(p0 + acol);
        av = make_float4(x1.x - x0.x, x1.y - x0.y, x1.z - x0.z, x1.w - x0.w);
    }
    bv = *(const float4*)(wp + acol);

    for (int k0 = 0; k0 < DIN; k0 += 8) {
        if (k0) __syncthreads();   // previous compute done before overwrite
        As[acol + 0][arow] = av.x; As[acol + 1][arow] = av.y;
        As[acol + 2][arow] = av.z; As[acol + 3][arow] = av.w;
        Bs[acol + 0][arow] = bv.x; Bs[acol + 1][arow] = bv.y;
        Bs[acol + 2][arow] = bv.z; Bs[acol + 3][arow] = bv.w;
        __syncthreads();

        // prefetch next K-slice into registers (overlaps with compute below)
        int kn = k0 + 8;
        if (kn < DIN) {
            av = make_float4(0.f, 0.f, 0.f, 0.f);
            if (mval) {
                float4 x1 = *(const float4*)(p1 + kn + acol);
                float4 x0 = *(const float4*)(p0 + kn + acol);
                av = make_float4(x1.x - x0.x, x1.y - x0.y,
                                 x1.z - x0.z, x1.w - x0.w);
            }
            bv = *(const float4*)(wp + kn + acol);
        }

        #pragma unroll
        for (int kk = 0; kk < 8; kk++) {
            float4 a0 = *(const float4*)&As[kk][ty * 8];
            float4 a1 = *(const float4*)&As[kk][ty * 8 + 4];
            float4 b0 = *(const float4*)&Bs[kk][tx * 8];
            float4 b1 = *(const float4*)&Bs[kk][tx * 8 + 4];
            float a[8] = {a0.x, a0.y, a0.z, a0.w, a1.x, a1.y, a1.z, a1.w};
            float b[8] = {b0.x, b0.y, b0.z, b0.w, b1.x, b1.y, b1.z, b1.w};
            #pragma unroll
            for (int i = 0; i < 8; i++)
                #pragma unroll
                for (int j = 0; j < 8; j++) acc[i][j] += a[i] * b[j];
        }
    }

    #pragma unroll
    for (int i = 0; i < 8; i++) {
        int mm = bm + ty * 8 + i;
        if (mm < MV) {
            float4 o0 = make_float4(acc[i][0], acc[i][1], acc[i][2], acc[i][3]);
            float4 o1 = make_float4(acc[i][4], acc[i][5], acc[i][6], acc[i][7]);
            float* cp = g_vin + (size_t)mm * DG + bn + tx * 8;
            *(float4*)(cp)     = o0;
            *(float4*)(cp + 4) = o1;
        }
    }
}

// ---------------------------------------------------------------------------
// Scan: one warp per batch element. g lives in registers (16 floats/lane,
// element idx = i*128 + lane*4 + c). Fast path when W_rec == I (elementwise),
// general fallback otherwise.
__global__ void __launch_bounds__(32) scan_k(const float* __restrict__ Wr,
                                             float* __restrict__ out) {
    const int b    = blockIdx.x;
    const int lane = threadIdx.x;
    const int off  = lane * 4;   // per-lane base within a 128-chunk

    float g[16];

    // --- g0: load relu'd preactivation, normalize, emit t=0 ---
    {
        const float* gp = g_g0 + (size_t)b * DG;
        float s = 0.0f;
        #pragma unroll
        for (int i = 0; i < 4; i++) {
            float4 v = *(const float4*)(gp + i * 128 + off);
            g[4 * i + 0] = v.x; g[4 * i + 1] = v.y;
            g[4 * i + 2] = v.z; g[4 * i + 3] = v.w;
        }
        #pragma unroll
        for (int i = 0; i < 16; i++) s += g[i] * g[i];
        #pragma unroll
        for (int o = 16; o > 0; o >>= 1) s += __shfl_xor_sync(0xffffffffu, s, o);
        float inv = 1.0f / fmaxf(sqrtf(s), EPS_);
        #pragma unroll
        for (int i = 0; i < 16; i++) g[i] *= inv;
        float* op = out + (size_t)b * T_ * DG;
        #pragma unroll
        for (int i = 0; i < 4; i++)
            *(float4*)(op + i * 128 + off) =
                make_float4(g[4 * i], g[4 * i + 1], g[4 * i + 2], g[4 * i + 3]);
    }

    if (g_notI == 0) {
        // ---- fast path: W_rec == identity ----
        float v[16];
        {
            const float* vp = g_vin + (size_t)b * DG;   // t = 0
            #pragma unroll
            for (int i = 0; i < 4; i++) {
                float4 q = *(const float4*)(vp + i * 128 + off);
                v[4 * i + 0] = q.x; v[4 * i + 1] = q.y;
                v[4 * i + 2] = q.z; v[4 * i + 3] = q.w;
            }
        }
        for (int t = 0; t < TV; t++) {
            float vn[16];
            if (t + 1 < TV) {
                const float* vp = g_vin + ((size_t)(t + 1) * B_ + b) * DG;
                #pragma unroll
                for (int i = 0; i < 4; i++) {
                    float4 q = *(const float4*)(vp + i * 128 + off);
                    vn[4 * i + 0] = q.x; vn[4 * i + 1] = q.y;
                    vn[4 * i + 2] = q.z; vn[4 * i + 3] = q.w;
                }
            }
            float s = 0.0f;
            #pragma unroll
            for (int i = 0; i < 16; i++) {
                float x = fmaxf(g[i] + v[i], 0.0f);
                g[i] = x;
                s += x * x;
            }
            #pragma unroll
            for (int o = 16; o > 0; o >>= 1)
                s += __shfl_xor_sync(0xffffffffu, s, o);
            float inv = 1.0f / fmaxf(sqrtf(s), EPS_);
            #pragma unroll
            for (int i = 0; i < 16; i++) g[i] *= inv;

            float* op = out + ((size_t)b * T_ + (t + 1)) * DG;
            #pragma unroll
            for (int i = 0; i < 4; i++)
                *(float4*)(op + i * 128 + off) =
                    make_float4(g[4 * i], g[4 * i + 1], g[4 * i + 2], g[4 * i + 3]);

            if (t + 1 < TV) {
                #pragma unroll
                for (int i = 0; i < 16; i++) v[i] = vn[i];
            }
        }
    } else {
        // ---- general path: full g @ W_rec^T per step (correct, slow) ----
        __shared__ float gs[DG];
        for (int t = 0; t < TV; t++) {
            #pragma unroll
            for (int i = 0; i < 4; i++)
                #pragma unroll
                for (int c = 0; c < 4; c++)
                    gs[i * 128 + off + c] = g[4 * i + c];
            __syncwarp();

            const float* vrow = g_vin + ((size_t)t * B_ + b) * DG;
            float y[16];
            float s = 0.0f;
            #pragma unroll
            for (int i = 0; i < 4; i++) {
                #pragma unroll
                for (int c = 0; c < 4; c++) {
                    int j = i * 128 + off + c;
                    float acc = vrow[j];
                    const float* wrow = Wr + (size_t)j * DG;
                    for (int k = 0; k < DG; k++) acc += gs[k] * wrow[k];
                    float x = fmaxf(acc, 0.0f);
                    y[4 * i + c] = x;
                    s += x * x;
                }
            }
            #pragma unroll
            for (int o = 16; o > 0; o >>= 1)
                s += __shfl_xor_sync(0xffffffffu, s, o);
            float inv = 1.0f / fmaxf(sqrtf(s), EPS_);
            #pragma unroll
            for (int i = 0; i < 16; i++) g[i] = y[i] * inv;

            float* op = out + ((size_t)b * T_ + (t + 1)) * DG;
            #pragma unroll
            for (int i = 0; i < 4; i++)
                *(float4*)(op + i * 128 + off) =
                    make_float4(g[4 * i], g[4 * i + 1], g[4 * i + 2], g[4 * i + 3]);
            __syncwarp();   // all lanes done reading gs before next publish
        }
    }
}

// ---------------------------------------------------------------------------
extern "C" void kernel_launch(void* const* d_in, const int* in_sizes, int n_in,
                              void* d_out, int out_size) {
    (void)in_sizes; (void)n_in; (void)out_size;
    const float* L   = (const float*)d_in[0];
    const float* W1  = (const float*)d_in[1];
    const float* b1  = (const float*)d_in[2];
    const float* W2  = (const float*)d_in[3];
    const float* b2  = (const float*)d_in[4];
    const float* W3  = (const float*)d_in[5];
    const float* b3  = (const float*)d_in[6];
    const float* Wr  = (const float*)d_in[7];
    const float* Win = (const float*)d_in[8];
    float* out = (float*)d_out;

    reset_flag_k<<<1, 1>>>();
    check_id_k<<<(DG * DG + 255) / 256, 256>>>(Wr);

    // MLP head: x0 rows stride T_*DIN within latents
    mlp_gemm_k<<<DHID / 64, 256>>>(L, T_ * DIN, W1, b1, /*stage=*/0, DHID, DIN);
    mlp_gemm_k<<<DG   / 64, 256>>>(L, DHID,     W2, b2, /*stage=*/1, DG,   DHID);
    mlp_gemm_k<<<DG   / 64, 256>>>(L, DG,       W3, b3, /*stage=*/2, DG,   DG);

    // vin GEMM (dominant): grid = (N/128, ceil(M/128))
    dim3 vgrid(DG / 128, (MV + 127) / 128);
    vin_gemm_k<<<vgrid, 256>>>(L, Win);

    // Sequential scan: one warp per batch element
    scan_k<<<B_, 32>>>(Wr, out);
}

// round 4
// speedup vs baseline: 1.5274x; 1.5274x over previous
#include <cuda_runtime.h>
#include <cuda_bf16.h>
#include <cstdint>

// ---------------------------------------------------------------------------
// GridCell: B=64, T=512, D_IN=1024, D_HID=1024, D_G=512
// vin GEMM runs on tensor cores via mma.sync (bf16, split hi/lo for fp32-class
// accuracy) — tcgen05 is unavailable because the harness targets compute_103
// (no 'a'), so only family-portable PTX (sm_80+ mma.sync/ldmatrix/cp.async).
// ---------------------------------------------------------------------------

namespace {
constexpr int B_   = 64;
constexpr int T_   = 512;
constexpr int DIN  = 1024;
constexpr int DHID = 1024;
constexpr int DG   = 512;
constexpr int TV   = T_ - 1;        // 511
constexpr int MV   = TV * B_;       // 32704 rows in the vin GEMM
constexpr float EPS_ = 1e-6f;

// vin GEMM tiling (mma.sync path)
constexpr int BM = 128;
constexpr int BN = 128;
constexpr int BK = 32;              // bf16 elems per K slab
constexpr int NSTAGE_IT = DIN / BK; // 32 K iterations
constexpr int ROWB = 80;            // padded smem row stride in bytes (32*2+16)
constexpr int TILE_B = 128 * ROWB;  // 10240 bytes per (128 x 32) bf16 tile
constexpr int STG_B  = 4 * TILE_B;  // Ahi,Alo,Bhi,Blo = 40960 per stage
constexpr int VIN_SMEM = 2 * STG_B + 128;
}

// ---- scratch ----
__device__ float g_vin[(size_t)MV * DG];   // [t][b][g]
__device__ float g_h1[B_ * DHID];
__device__ float g_h2[B_ * DG];
__device__ float g_g0[B_ * DG];            // relu'd, pre-normalization
__device__ int   g_notI;
__device__ __nv_bfloat16 g_Whi[(size_t)DG * DIN];
__device__ __nv_bfloat16 g_Wlo[(size_t)DG * DIN];

// ---------------------------------------------------------------------------
__device__ __forceinline__ uint32_t smem_u32(const void* p) {
    uint32_t a;
    asm("{ .reg .u64 t; cvta.to.shared.u64 t, %1; cvt.u32.u64 %0, t; }"
        : "=r"(a) : "l"(p));
    return a;
}

__device__ __forceinline__ void ldsm_x4(uint32_t* r, uint32_t addr) {
    asm volatile("ldmatrix.sync.aligned.m8n8.x4.shared.b16 {%0,%1,%2,%3}, [%4];"
                 : "=r"(r[0]), "=r"(r[1]), "=r"(r[2]), "=r"(r[3]) : "r"(addr));
}
__device__ __forceinline__ void ldsm_x2(uint32_t* r, uint32_t addr) {
    asm volatile("ldmatrix.sync.aligned.m8n8.x2.shared.b16 {%0,%1}, [%2];"
                 : "=r"(r[0]), "=r"(r[1]) : "r"(addr));
}

__device__ __forceinline__ void mma_bf16(float* c, const uint32_t* a,
                                         const uint32_t* b) {
    asm volatile(
        "mma.sync.aligned.m16n8k16.row.col.f32.bf16.bf16.f32 "
        "{%0,%1,%2,%3}, {%4,%5,%6,%7}, {%8,%9}, {%0,%1,%2,%3};"
        : "+f"(c[0]), "+f"(c[1]), "+f"(c[2]), "+f"(c[3])
        : "r"(a[0]), "r"(a[1]), "r"(a[2]), "r"(a[3]), "r"(b[0]), "r"(b[1]));
}

__device__ __forceinline__ void cp_async16(uint32_t saddr, const void* gaddr) {
    asm volatile("cp.async.cg.shared.global [%0], [%1], 16;"
                 :: "r"(saddr), "l"(gaddr) : "memory");
}
__device__ __forceinline__ void cp_commit() {
    asm volatile("cp.async.commit_group;" ::: "memory");
}
__device__ __forceinline__ void cp_wait0() {
    asm volatile("cp.async.wait_group 0;" ::: "memory");
}

// split a float into bf16 hi + lo
__device__ __forceinline__ void split2(float x, float y, uint32_t& h, uint32_t& l) {
    __nv_bfloat16 hx = __float2bfloat16(x);
    __nv_bfloat16 hy = __float2bfloat16(y);
    __nv_bfloat16 lx = __float2bfloat16(x - __bfloat162float(hx));
    __nv_bfloat16 ly = __float2bfloat16(y - __bfloat162float(hy));
    h = ((uint32_t)__bfloat16_as_ushort(hy) << 16) | __bfloat16_as_ushort(hx);
    l = ((uint32_t)__bfloat16_as_ushort(ly) << 16) | __bfloat16_as_ushort(lx);
}

// ---------------------------------------------------------------------------
__global__ void reset_flag_k() { g_notI = 0; }

__global__ void check_id_k(const float* __restrict__ Wr) {
    int i = blockIdx.x * blockDim.x + threadIdx.x;
    if (i >= DG * DG) return;
    int r = i >> 9;
    int c = i & (DG - 1);
    float e = (r == c) ? 1.0f : 0.0f;
    if (Wr[i] != e) g_notI = 1;
}

// Split W_in into bf16 hi/lo once (L2-resident thereafter)
__global__ void prep_w_k(const float* __restrict__ W) {
    int i = blockIdx.x * blockDim.x + threadIdx.x;   // float4 index
    const float4 v = ((const float4*)W)[i];
    uint32_t h0, l0, h1, l1;
    split2(v.x, v.y, h0, l0);
    split2(v.z, v.w, h1, l1);
    ((uint2*)g_Whi)[i] = make_uint2(h0, h1);
    ((uint2*)g_Wlo)[i] = make_uint2(l0, l1);
}

// ---------------------------------------------------------------------------
// MLP GEMM with register-prefetch double buffering. M = 64.
__global__ void __launch_bounds__(256) mlp_gemm_k(const float* __restrict__ Ain, int lda,
                           const float* __restrict__ W,
                           const float* __restrict__ bias,
                           int stage, int N, int K) {
    __shared__ float As[16][64];
    __shared__ float Bs[16][64];

    const float* A = (stage == 0) ? Ain : (stage == 1 ? g_h1 : g_h2);
    float*       C = (stage == 0) ? g_h1 : (stage == 1 ? g_h2 : g_g0);

    const int tid  = threadIdx.x;
    const int bn   = blockIdx.x * 64;
    const int lrow = tid >> 2;
    const int lcol = (tid & 3) << 2;
    const int tx   = tid & 15;
    const int ty   = tid >> 4;

    float acc[4][4];
    #pragma unroll
    for (int i = 0; i < 4; i++)
        #pragma unroll
        for (int j = 0; j < 4; j++) acc[i][j] = 0.0f;

    float4 a4 = *(const float4*)(A + (size_t)lrow * lda + lcol);
    float4 b4 = *(const float4*)(W + (size_t)(bn + lrow) * K + lcol);

    for (int k0 = 0; k0 < K; k0 += 16) {
        if (k0) __syncthreads();
        As[lcol + 0][lrow] = a4.x; As[lcol + 1][lrow] = a4.y;
        As[lcol + 2][lrow] = a4.z; As[lcol + 3][lrow] = a4.w;
        Bs[lcol + 0][lrow] = b4.x; Bs[lcol + 1][lrow] = b4.y;
        Bs[lcol + 2][lrow] = b4.z; Bs[lcol + 3][lrow] = b4.w;
        __syncthreads();

        int kn = k0 + 16;
        if (kn < K) {
            a4 = *(const float4*)(A + (size_t)lrow * lda + kn + lcol);
            b4 = *(const float4*)(W + (size_t)(bn + lrow) * K + kn + lcol);
        }

        #pragma unroll
        for (int kk = 0; kk < 16; kk++) {
            float4 av = *(const float4*)&As[kk][ty * 4];
            float4 bv = *(const float4*)&Bs[kk][tx * 4];
            float a[4] = {av.x, av.y, av.z, av.w};
            float b[4] = {bv.x, bv.y, bv.z, bv.w};
            #pragma unroll
            for (int i = 0; i < 4; i++)
                #pragma unroll
                for (int j = 0; j < 4; j++) acc[i][j] += a[i] * b[j];
        }
    }

    #pragma unroll
    for (int i = 0; i < 4; i++) {
        int m = ty * 4 + i;
        #pragma unroll
        for (int j = 0; j < 4; j++) {
            int n = bn + tx * 4 + j;
            float v = acc[i][j] + bias[n];
            C[(size_t)m * N + n] = fmaxf(v, 0.0f);
        }
    }
}

// ---------------------------------------------------------------------------
// vin GEMM on mma.sync bf16 (split hi/lo).
// g_vin[m, n] = sum_k vel[m,k] * W_in[n,k],  m = t*64 + b.
// Block 128x128, 8 warps (2m x 4n), warp tile 64x32, K slab 32, double buffer.
__global__ void __launch_bounds__(256, 1) vin_mma_k(const float* __restrict__ L) {
    extern __shared__ char dsm[];
    const int tid  = threadIdx.x;
    const int wid  = tid >> 5;
    const int lane = tid & 31;
    const int bn   = blockIdx.x * BN;
    const int bm   = blockIdx.y * BM;

    const int wm = (wid & 1) * 64;      // warp m offset
    const int wn = (wid >> 1) * 32;     // warp n offset

    uint32_t sbase = (smem_u32(dsm) + 127u) & ~127u;
    // stage layout: [Ahi | Alo | Bhi | Blo], each 128 rows * 80 B
    const uint32_t stA[2] = {sbase, sbase + STG_B};

    // ---- per-thread load descriptors ----
    // A: thread covers row (tid>>1), 16 floats at k-offset (tid&1)*16
    const int arow = tid >> 1;
    const int aj   = (tid & 1) * 16;              // float offset in slab
    const int am   = bm + arow;
    const bool amv = (am < MV);
    const float* ap0 = L;
    if (amv) {
        int tt = am >> 6, bb = am & 63;
        ap0 = L + ((size_t)bb * T_ + tt) * DIN;
    }
    const uint32_t aoff = (uint32_t)(arow * ROWB + aj * 2);  // bytes (bf16)

    // B: thread covers n-row (tid>>1), two 16B chunks at (tid&1)*2
    const int brow = tid >> 1;
    const int bj   = (tid & 1) * 2;               // 16B-chunk index (of 4)
    const __nv_bfloat16* bh_g = g_Whi + (size_t)(bn + brow) * DIN + bj * 8;
    const __nv_bfloat16* bl_g = g_Wlo + (size_t)(bn + brow) * DIN + bj * 8;
    const uint32_t boff = (uint32_t)(brow * ROWB + bj * 16);

    float4 d[4];   // A prefetch regs (vel, fp32)

    auto loadA = [&](int k0) {
        #pragma unroll
        for (int q = 0; q < 4; q++) {
            if (amv) {
                const float* p = ap0 + k0 + aj + q * 4;
                float4 x0 = *(const float4*)p;
                float4 x1 = *(const float4*)(p + DIN);
                d[q] = make_float4(x1.x - x0.x, x1.y - x0.y,
                                   x1.z - x0.z, x1.w - x0.w);
            } else {
                d[q] = make_float4(0.f, 0.f, 0.f, 0.f);
            }
        }
    };
    auto storeA = [&](uint32_t st) {
        uint32_t hi[8], lo[8];
        #pragma unroll
        for (int q = 0; q < 4; q++) {
            split2(d[q].x, d[q].y, hi[2 * q], lo[2 * q]);
            split2(d[q].z, d[q].w, hi[2 * q + 1], lo[2 * q + 1]);
        }
        #pragma unroll
        for (int q = 0; q < 2; q++) {
            uint4 vh = make_uint4(hi[4 * q], hi[4 * q + 1], hi[4 * q + 2], hi[4 * q + 3]);
            uint4 vl = make_uint4(lo[4 * q], lo[4 * q + 1], lo[4 * q + 2], lo[4 * q + 3]);
            asm volatile("st.shared.v4.b32 [%0], {%1,%2,%3,%4};"
                         :: "r"(st + aoff + q * 16),
                            "r"(vh.x), "r"(vh.y), "r"(vh.z), "r"(vh.w) : "memory");
            asm volatile("st.shared.v4.b32 [%0], {%1,%2,%3,%4};"
                         :: "r"(st + TILE_B + aoff + q * 16),
                            "r"(vl.x), "r"(vl.y), "r"(vl.z), "r"(vl.w) : "memory");
        }
    };
    auto loadB = [&](int k0, uint32_t st) {
        #pragma unroll
        for (int c = 0; c < 2; c++) {
            cp_async16(st + 2 * TILE_B + boff + c * 16, bh_g + k0 + c * 8);
            cp_async16(st + 3 * TILE_B + boff + c * 16, bl_g + k0 + c * 8);
        }
        cp_commit();
    };

    float acc[4][4][4];
    #pragma unroll
    for (int i = 0; i < 4; i++)
        #pragma unroll
        for (int j = 0; j < 4; j++)
            #pragma unroll
            for (int q = 0; q < 4; q++) acc[i][j][q] = 0.0f;

    // ldmatrix addresses (within a stage)
    const uint32_t a_off = (uint32_t)((wm + (lane & 15)) * ROWB + (lane >> 4) * 16);
    const uint32_t b_off = (uint32_t)((wn + (lane & 7)) * ROWB + ((lane >> 3) & 1) * 16);

    // ---- prologue: stage 0 ----
    loadA(0);
    loadB(0, stA[0]);
    storeA(stA[0]);

    for (int s = 0; s < NSTAGE_IT; s++) {
        const uint32_t cur = stA[s & 1];
        const uint32_t nxt = stA[(s + 1) & 1];

        cp_wait0();
        __syncthreads();                   // stage s (A stores + B cp.async) ready

        if (s + 1 < NSTAGE_IT) {
            loadA((s + 1) * BK);
            loadB((s + 1) * BK, nxt);
        }

        // ---- compute stage s: 2 x k16 ----
        #pragma unroll
        for (int kk = 0; kk < 2; kk++) {
            uint32_t ah[4][4], al[4][4], bh[4][2], bl[4][2];
            #pragma unroll
            for (int mi = 0; mi < 4; mi++) {
                uint32_t ad = cur + a_off + mi * 16 * ROWB + kk * 32;
                ldsm_x4(ah[mi], ad);
                ldsm_x4(al[mi], ad + TILE_B);
            }
            #pragma unroll
            for (int nj = 0; nj < 4; nj++) {
                uint32_t bd = cur + 2 * TILE_B + b_off + nj * 8 * ROWB + kk * 32;
                ldsm_x2(bh[nj], bd);
                ldsm_x2(bl[nj], bd + TILE_B);
            }
            #pragma unroll
            for (int mi = 0; mi < 4; mi++)
                #pragma unroll
                for (int nj = 0; nj < 4; nj++) {
                    mma_bf16(acc[mi][nj], ah[mi], bh[nj]);
                    mma_bf16(acc[mi][nj], ah[mi], bl[nj]);
                    mma_bf16(acc[mi][nj], al[mi], bh[nj]);
                }
        }

        if (s + 1 < NSTAGE_IT) storeA(nxt);
        __syncthreads();                   // reads of cur done; nxt A stores done
    }

    // ---- epilogue: C frags -> g_vin ----
    #pragma unroll
    for (int mi = 0; mi < 4; mi++) {
        int r0 = bm + wm + mi * 16 + (lane >> 2);
        #pragma unroll
        for (int nj = 0; nj < 4; nj++) {
            int cc = bn + wn + nj * 8 + (lane & 3) * 2;
            if (r0 < MV)
                *(float2*)(g_vin + (size_t)r0 * DG + cc) =
                    make_float2(acc[mi][nj][0], acc[mi][nj][1]);
            if (r0 + 8 < MV)
                *(float2*)(g_vin + (size_t)(r0 + 8) * DG + cc) =
                    make_float2(acc[mi][nj][2], acc[mi][nj][3]);
        }
    }
}

// ---------------------------------------------------------------------------
// Scan: one warp per batch element, g resident in registers.
__global__ void __launch_bounds__(32) scan_k(const float* __restrict__ Wr,
                                             float* __restrict__ out) {
    const int b    = blockIdx.x;
    const int lane = threadIdx.x;
    const int off  = lane * 4;

    float g[16];

    {
        const float* gp = g_g0 + (size_t)b * DG;
        float s = 0.0f;
        #pragma unroll
        for (int i = 0; i < 4; i++) {
            float4 v = *(const float4*)(gp + i * 128 + off);
            g[4 * i + 0] = v.x; g[4 * i + 1] = v.y;
            g[4 * i + 2] = v.z; g[4 * i + 3] = v.w;
        }
        #pragma unroll
        for (int i = 0; i < 16; i++) s += g[i] * g[i];
        #pragma unroll
        for (int o = 16; o > 0; o >>= 1) s += __shfl_xor_sync(0xffffffffu, s, o);
        float inv = 1.0f / fmaxf(sqrtf(s), EPS_);
        #pragma unroll
        for (int i = 0; i < 16; i++) g[i] *= inv;
        float* op = out + (size_t)b * T_ * DG;
        #pragma unroll
        for (int i = 0; i < 4; i++)
            *(float4*)(op + i * 128 + off) =
                make_float4(g[4 * i], g[4 * i + 1], g[4 * i + 2], g[4 * i + 3]);
    }

    if (g_notI == 0) {
        float v[16];
        {
            const float* vp = g_vin + (size_t)b * DG;
            #pragma unroll
            for (int i = 0; i < 4; i++) {
                float4 q = *(const float4*)(vp + i * 128 + off);
                v[4 * i + 0] = q.x; v[4 * i + 1] = q.y;
                v[4 * i + 2] = q.z; v[4 * i + 3] = q.w;
            }
        }
        for (int t = 0; t < TV; t++) {
            float vn[16];
            if (t + 1 < TV) {
                const float* vp = g_vin + ((size_t)(t + 1) * B_ + b) * DG;
                #pragma unroll
                for (int i = 0; i < 4; i++) {
                    float4 q = *(const float4*)(vp + i * 128 + off);
                    vn[4 * i + 0] = q.x; vn[4 * i + 1] = q.y;
                    vn[4 * i + 2] = q.z; vn[4 * i + 3] = q.w;
                }
            }
            float s = 0.0f;
            #pragma unroll
            for (int i = 0; i < 16; i++) {
                float x = fmaxf(g[i] + v[i], 0.0f);
                g[i] = x;
                s += x * x;
            }
            #pragma unroll
            for (int o = 16; o > 0; o >>= 1)
                s += __shfl_xor_sync(0xffffffffu, s, o);
            float inv = 1.0f / fmaxf(sqrtf(s), EPS_);
            #pragma unroll
            for (int i = 0; i < 16; i++) g[i] *= inv;

            float* op = out + ((size_t)b * T_ + (t + 1)) * DG;
            #pragma unroll
            for (int i = 0; i < 4; i++)
                *(float4*)(op + i * 128 + off) =
                    make_float4(g[4 * i], g[4 * i + 1], g[4 * i + 2], g[4 * i + 3]);

            if (t + 1 < TV) {
                #pragma unroll
                for (int i = 0; i < 16; i++) v[i] = vn[i];
            }
        }
    } else {
        __shared__ float gs[DG];
        for (int t = 0; t < TV; t++) {
            #pragma unroll
            for (int i = 0; i < 4; i++)
                #pragma unroll
                for (int c = 0; c < 4; c++)
                    gs[i * 128 + off + c] = g[4 * i + c];
            __syncwarp();

            const float* vrow = g_vin + ((size_t)t * B_ + b) * DG;
            float y[16];
            float s = 0.0f;
            #pragma unroll
            for (int i = 0; i < 4; i++) {
                #pragma unroll
                for (int c = 0; c < 4; c++) {
                    int j = i * 128 + off + c;
                    float acc = vrow[j];
                    const float* wrow = Wr + (size_t)j * DG;
                    for (int k = 0; k < DG; k++) acc += gs[k] * wrow[k];
                    float x = fmaxf(acc, 0.0f);
                    y[4 * i + c] = x;
                    s += x * x;
                }
            }
            #pragma unroll
            for (int o = 16; o > 0; o >>= 1)
                s += __shfl_xor_sync(0xffffffffu, s, o);
            float inv = 1.0f / fmaxf(sqrtf(s), EPS_);
            #pragma unroll
            for (int i = 0; i < 16; i++) g[i] = y[i] * inv;

            float* op = out + ((size_t)b * T_ + (t + 1)) * DG;
            #pragma unroll
            for (int i = 0; i < 4; i++)
                *(float4*)(op + i * 128 + off) =
                    make_float4(g[4 * i], g[4 * i + 1], g[4 * i + 2], g[4 * i + 3]);
            __syncwarp();
        }
    }
}

// ---------------------------------------------------------------------------
extern "C" void kernel_launch(void* const* d_in, const int* in_sizes, int n_in,
                              void* d_out, int out_size) {
    (void)in_sizes; (void)n_in; (void)out_size;
    const float* L   = (const float*)d_in[0];
    const float* W1  = (const float*)d_in[1];
    const float* b1  = (const float*)d_in[2];
    const float* W2  = (const float*)d_in[3];
    const float* b2  = (const float*)d_in[4];
    const float* W3  = (const float*)d_in[5];
    const float* b3  = (const float*)d_in[6];
    const float* Wr  = (const float*)d_in[7];
    const float* Win = (const float*)d_in[8];
    float* out = (float*)d_out;

    static bool attr_done = false;
    if (!attr_done) {
        cudaFuncSetAttribute(vin_mma_k,
                             cudaFuncAttributeMaxDynamicSharedMemorySize,
                             VIN_SMEM);
        attr_done = true;
    }

    reset_flag_k<<<1, 1>>>();
    check_id_k<<<(DG * DG + 255) / 256, 256>>>(Wr);

    mlp_gemm_k<<<DHID / 64, 256>>>(L, T_ * DIN, W1, b1, 0, DHID, DIN);
    mlp_gemm_k<<<DG   / 64, 256>>>(L, DHID,     W2, b2, 1, DG,   DHID);
    mlp_gemm_k<<<DG   / 64, 256>>>(L, DG,       W3, b3, 2, DG,   DG);

    prep_w_k<<<(DG * DIN / 4) / 256, 256>>>(Win);

    dim3 vgrid(DG / BN, (MV + BM - 1) / BM);   // (4, 256)
    vin_mma_k<<<vgrid, 256, VIN_SMEM>>>(L);

    scan_k<<<B_, 32>>>(Wr, out);
}

// round 5
// speedup vs baseline: 2.8340x; 1.8555x over previous
#include <cuda_runtime.h>
#include <cuda_fp16.h>
#include <cstdint>

// ---------------------------------------------------------------------------
// GridCell: B=64, T=512, D_IN=1024, D_HID=1024, D_G=512
// vin GEMM: single-pass fp16 mma.sync (HMMA issue-bound on sm_103; tcgen05
// unavailable because harness targets compute_103 without the 'a' suffix).
// ---------------------------------------------------------------------------

namespace {
constexpr int B_   = 64;
constexpr int T_   = 512;
constexpr int DIN  = 1024;
constexpr int DHID = 1024;
constexpr int DG   = 512;
constexpr int TV   = T_ - 1;        // 511
constexpr int MV   = TV * B_;       // 32704 rows in the vin GEMM
constexpr float EPS_ = 1e-6f;

// vin GEMM tiling
constexpr int BM = 128;
constexpr int BN = 128;
constexpr int BK = 32;              // fp16 elems per K slab
constexpr int NIT = DIN / BK;       // 32 K iterations
constexpr int ROWB = 80;            // padded smem row stride bytes (64 + 16)
constexpr int TILE_B = 128 * ROWB;  // 10240 per (128 x 32) fp16 tile
constexpr int STG_B  = 2 * TILE_B;  // A + B per stage = 20480
constexpr int VIN_SMEM = 2 * STG_B + 128;  // ~41 KB (fits default 48 KB)
}

// ---- scratch ----
__device__ float g_vin[(size_t)MV * DG];   // [t][b][g]
__device__ float g_h1[B_ * DHID];
__device__ float g_h2[B_ * DG];
__device__ float g_g0[B_ * DG];            // relu'd, pre-normalization
__device__ float g_part[8 * B_ * DHID];    // split-K partials (max 2 MB)
__device__ int   g_notI;
__device__ __half g_Wh[(size_t)DG * DIN];  // W_in in fp16

// ---------------------------------------------------------------------------
__device__ __forceinline__ uint32_t smem_u32(const void* p) {
    uint32_t a;
    asm("{ .reg .u64 t; cvta.to.shared.u64 t, %1; cvt.u32.u64 %0, t; }"
        : "=r"(a) : "l"(p));
    return a;
}

__device__ __forceinline__ void ldsm_x4(uint32_t* r, uint32_t addr) {
    asm volatile("ldmatrix.sync.aligned.m8n8.x4.shared.b16 {%0,%1,%2,%3}, [%4];"
                 : "=r"(r[0]), "=r"(r[1]), "=r"(r[2]), "=r"(r[3]) : "r"(addr));
}
__device__ __forceinline__ void ldsm_x2(uint32_t* r, uint32_t addr) {
    asm volatile("ldmatrix.sync.aligned.m8n8.x2.shared.b16 {%0,%1}, [%2];"
                 : "=r"(r[0]), "=r"(r[1]) : "r"(addr));
}

__device__ __forceinline__ void mma_f16(float* c, const uint32_t* a,
                                        const uint32_t* b) {
    asm volatile(
        "mma.sync.aligned.m16n8k16.row.col.f32.f16.f16.f32 "
        "{%0,%1,%2,%3}, {%4,%5,%6,%7}, {%8,%9}, {%0,%1,%2,%3};"
        : "+f"(c[0]), "+f"(c[1]), "+f"(c[2]), "+f"(c[3])
        : "r"(a[0]), "r"(a[1]), "r"(a[2]), "r"(a[3]), "r"(b[0]), "r"(b[1]));
}

__device__ __forceinline__ void cp_async16(uint32_t saddr, const void* gaddr) {
    asm volatile("cp.async.cg.shared.global [%0], [%1], 16;"
                 :: "r"(saddr), "l"(gaddr) : "memory");
}
__device__ __forceinline__ void cp_commit() {
    asm volatile("cp.async.commit_group;" ::: "memory");
}
__device__ __forceinline__ void cp_wait0() {
    asm volatile("cp.async.wait_group 0;" ::: "memory");
}

__device__ __forceinline__ uint32_t pack_h2(float x, float y) {
    __half2 h = __floats2half2_rn(x, y);
    return *reinterpret_cast<uint32_t*>(&h);
}

// ---------------------------------------------------------------------------
__global__ void reset_flag_k() { g_notI = 0; }

__global__ void check_id_k(const float* __restrict__ Wr) {
    int i = blockIdx.x * blockDim.x + threadIdx.x;
    if (i >= DG * DG) return;
    int r = i >> 9;
    int c = i & (DG - 1);
    float e = (r == c) ? 1.0f : 0.0f;
    if (Wr[i] != e) g_notI = 1;
}

// Convert W_in to fp16 once (1 MB, L2-resident thereafter)
__global__ void prep_w_k(const float* __restrict__ W) {
    int i = blockIdx.x * blockDim.x + threadIdx.x;   // float4 index
    const float4 v = ((const float4*)W)[i];
    ((uint2*)g_Wh)[i] = make_uint2(pack_h2(v.x, v.y), pack_h2(v.z, v.w));
}

// ---------------------------------------------------------------------------
// MLP split-K: partial GEMM (no bias/relu). M=64, BN=64, k-slice klen.
// grid (N/64, KS). part[(ks*64 + m)*N + n] = A[m, ks*klen .. ]*W[n, ..]
__global__ void __launch_bounds__(256) mlp_part_k(const float* __restrict__ Ain,
                                                  int lda, int stage,
                                                  const float* __restrict__ W,
                                                  int N, int klen) {
    __shared__ float As[16][64];
    __shared__ float Bs[16][64];

    const float* A = (stage == 0) ? Ain : (stage == 1 ? g_h1 : g_h2);

    const int tid  = threadIdx.x;
    const int bn   = blockIdx.x * 64;
    const int kofs = blockIdx.y * klen;
    const int lrow = tid >> 2;
    const int lcol = (tid & 3) << 2;
    const int tx   = tid & 15;
    const int ty   = tid >> 4;

    float acc[4][4];
    #pragma unroll
    for (int i = 0; i < 4; i++)
        #pragma unroll
        for (int j = 0; j < 4; j++) acc[i][j] = 0.0f;

    const int K = lda == (T_ * DIN) ? DIN : lda;  // W row stride = full K
    float4 a4 = *(const float4*)(A + (size_t)lrow * lda + kofs + lcol);
    float4 b4 = *(const float4*)(W + (size_t)(bn + lrow) * K + kofs + lcol);

    for (int k0 = 0; k0 < klen; k0 += 16) {
        if (k0) __syncthreads();
        As[lcol + 0][lrow] = a4.x; As[lcol + 1][lrow] = a4.y;
        As[lcol + 2][lrow] = a4.z; As[lcol + 3][lrow] = a4.w;
        Bs[lcol + 0][lrow] = b4.x; Bs[lcol + 1][lrow] = b4.y;
        Bs[lcol + 2][lrow] = b4.z; Bs[lcol + 3][lrow] = b4.w;
        __syncthreads();

        int kn = k0 + 16;
        if (kn < klen) {
            a4 = *(const float4*)(A + (size_t)lrow * lda + kofs + kn + lcol);
            b4 = *(const float4*)(W + (size_t)(bn + lrow) * K + kofs + kn + lcol);
        }

        #pragma unroll
        for (int kk = 0; kk < 16; kk++) {
            float4 av = *(const float4*)&As[kk][ty * 4];
            float4 bv = *(const float4*)&Bs[kk][tx * 4];
            float a[4] = {av.x, av.y, av.z, av.w};
            float b[4] = {bv.x, bv.y, bv.z, bv.w};
            #pragma unroll
            for (int i = 0; i < 4; i++)
                #pragma unroll
                for (int j = 0; j < 4; j++) acc[i][j] += a[i] * b[j];
        }
    }

    #pragma unroll
    for (int i = 0; i < 4; i++) {
        int m = ty * 4 + i;
        #pragma unroll
        for (int j = 0; j < 4; j++) {
            int n = bn + tx * 4 + j;
            g_part[((size_t)blockIdx.y * 64 + m) * N + n] = acc[i][j];
        }
    }
}

// reduce partials + bias + relu -> stage output
__global__ void mlp_red_k(const float* __restrict__ bias, int stage,
                          int N, int KS) {
    int i = blockIdx.x * blockDim.x + threadIdx.x;   // 64*N total
    int m = i / N;
    int n = i - m * N;
    float s = 0.0f;
    for (int k = 0; k < KS; k++)
        s += g_part[((size_t)k * 64 + m) * N + n];
    float v = fmaxf(s + bias[n], 0.0f);
    float* C = (stage == 0) ? g_h1 : (stage == 1 ? g_h2 : g_g0);
    C[(size_t)m * N + n] = v;
}

// ---------------------------------------------------------------------------
// vin GEMM: single-pass fp16 mma.sync.
// g_vin[m, n] = sum_k vel[m,k]*W_in[n,k],  m = t*64 + b.
// Block 128x128, 8 warps (2m x 4n), warp tile 64x32, K slab 32, double buffer.
__global__ void __launch_bounds__(256, 2) vin_mma_k(const float* __restrict__ L) {
    extern __shared__ char dsm[];
    const int tid  = threadIdx.x;
    const int wid  = tid >> 5;
    const int lane = tid & 31;
    const int bn   = blockIdx.x * BN;
    const int bm   = blockIdx.y * BM;

    const int wm = (wid & 1) * 64;
    const int wn = (wid >> 1) * 32;

    uint32_t sbase = (smem_u32(dsm) + 127u) & ~127u;
    const uint32_t stA[2] = {sbase, sbase + STG_B};  // per stage: [A | B]

    // A: thread covers row (tid>>1), 16 floats at k-offset (tid&1)*16
    const int arow = tid >> 1;
    const int aseg = (tid & 1) * 16;
    const int am   = bm + arow;
    const bool amv = (am < MV);
    const float* ap0 = L;
    if (amv) {
        int tt = am >> 6, bb = am & 63;
        ap0 = L + ((size_t)bb * T_ + tt) * DIN;
    }
    const uint32_t aoff = (uint32_t)(arow * ROWB + aseg * 2);

    // B: thread covers n-row (tid>>1), one 32B chunk (tid&1)
    const int brow = tid >> 1;
    const int bch  = tid & 1;
    const __half* bg = g_Wh + (size_t)(bn + brow) * DIN + bch * 16;
    const uint32_t boff = (uint32_t)(brow * ROWB + bch * 32);

    float4 d[4];

    auto loadA = [&](int k0) {
        #pragma unroll
        for (int q = 0; q < 4; q++) {
            if (amv) {
                const float* p = ap0 + k0 + aseg + q * 4;
                float4 x0 = *(const float4*)p;
                float4 x1 = *(const float4*)(p + DIN);
                d[q] = make_float4(x1.x - x0.x, x1.y - x0.y,
                                   x1.z - x0.z, x1.w - x0.w);
            } else {
                d[q] = make_float4(0.f, 0.f, 0.f, 0.f);
            }
        }
    };
    auto storeA = [&](uint32_t st) {
        uint32_t h[8];
        #pragma unroll
        for (int q = 0; q < 4; q++) {
            h[2 * q]     = pack_h2(d[q].x, d[q].y);
            h[2 * q + 1] = pack_h2(d[q].z, d[q].w);
        }
        #pragma unroll
        for (int q = 0; q < 2; q++)
            asm volatile("st.shared.v4.b32 [%0], {%1,%2,%3,%4};"
                         :: "r"(st + aoff + q * 16),
                            "r"(h[4 * q]), "r"(h[4 * q + 1]),
                            "r"(h[4 * q + 2]), "r"(h[4 * q + 3]) : "memory");
    };
    auto loadB = [&](int k0, uint32_t st) {
        cp_async16(st + TILE_B + boff,      bg + k0);
        cp_async16(st + TILE_B + boff + 16, bg + k0 + 8);
        cp_commit();
    };

    float acc[4][4][4];
    #pragma unroll
    for (int i = 0; i < 4; i++)
        #pragma unroll
        for (int j = 0; j < 4; j++)
            #pragma unroll
            for (int q = 0; q < 4; q++) acc[i][j][q] = 0.0f;

    const uint32_t a_off = (uint32_t)((wm + (lane & 15)) * ROWB + (lane >> 4) * 16);
    const uint32_t b_off = (uint32_t)((wn + (lane & 7)) * ROWB + ((lane >> 3) & 1) * 16);

    loadA(0);
    loadB(0, stA[0]);
    storeA(stA[0]);

    for (int s = 0; s < NIT; s++) {
        const uint32_t cur = stA[s & 1];
        const uint32_t nxt = stA[(s + 1) & 1];

        cp_wait0();
        __syncthreads();

        if (s + 1 < NIT) {
            loadA((s + 1) * BK);
            loadB((s + 1) * BK, nxt);
        }

        #pragma unroll
        for (int kk = 0; kk < 2; kk++) {
            uint32_t ah[4][4], bh[4][2];
            #pragma unroll
            for (int mi = 0; mi < 4; mi++)
                ldsm_x4(ah[mi], cur + a_off + mi * 16 * ROWB + kk * 32);
            #pragma unroll
            for (int nj = 0; nj < 4; nj++)
                ldsm_x2(bh[nj], cur + TILE_B + b_off + nj * 8 * ROWB + kk * 32);
            #pragma unroll
            for (int mi = 0; mi < 4; mi++)
                #pragma unroll
                for (int nj = 0; nj < 4; nj++)
                    mma_f16(acc[mi][nj], ah[mi], bh[nj]);
        }

        if (s + 1 < NIT) storeA(nxt);
        __syncthreads();
    }

    #pragma unroll
    for (int mi = 0; mi < 4; mi++) {
        int r0 = bm + wm + mi * 16 + (lane >> 2);
        #pragma unroll
        for (int nj = 0; nj < 4; nj++) {
            int cc = bn + wn + nj * 8 + (lane & 3) * 2;
            if (r0 < MV)
                *(float2*)(g_vin + (size_t)r0 * DG + cc) =
                    make_float2(acc[mi][nj][0], acc[mi][nj][1]);
            if (r0 + 8 < MV)
                *(float2*)(g_vin + (size_t)(r0 + 8) * DG + cc) =
                    make_float2(acc[mi][nj][2], acc[mi][nj][3]);
        }
    }
}

// ---------------------------------------------------------------------------
// Scan: one warp per batch element, g resident in registers.
__device__ __forceinline__ float warp_inv_norm(const float* x) {
    float p[8];
    #pragma unroll
    for (int j = 0; j < 8; j++)
        p[j] = fmaf(x[2 * j + 1], x[2 * j + 1], x[2 * j] * x[2 * j]);
    float q0 = p[0] + p[1], q1 = p[2] + p[3], q2 = p[4] + p[5], q3 = p[6] + p[7];
    float s = (q0 + q1) + (q2 + q3);
    #pragma unroll
    for (int o = 16; o > 0; o >>= 1) s += __shfl_xor_sync(0xffffffffu, s, o);
    return (s > 1e-12f) ? rsqrtf(s) : (1.0f / EPS_);
}

__global__ void __launch_bounds__(32) scan_k(const float* __restrict__ Wr,
                                             float* __restrict__ out) {
    const int b    = blockIdx.x;
    const int lane = threadIdx.x;
    const int off  = lane * 4;

    float g[16];

    {
        const float* gp = g_g0 + (size_t)b * DG;
        #pragma unroll
        for (int i = 0; i < 4; i++) {
            float4 v = *(const float4*)(gp + i * 128 + off);
            g[4 * i + 0] = v.x; g[4 * i + 1] = v.y;
            g[4 * i + 2] = v.z; g[4 * i + 3] = v.w;
        }
        float inv = warp_inv_norm(g);
        #pragma unroll
        for (int i = 0; i < 16; i++) g[i] *= inv;
        float* op = out + (size_t)b * T_ * DG;
        #pragma unroll
        for (int i = 0; i < 4; i++)
            *(float4*)(op + i * 128 + off) =
                make_float4(g[4 * i], g[4 * i + 1], g[4 * i + 2], g[4 * i + 3]);
    }

    if (g_notI == 0) {
        float v[16];
        {
            const float* vp = g_vin + (size_t)b * DG;
            #pragma unroll
            for (int i = 0; i < 4; i++) {
                float4 q = *(const float4*)(vp + i * 128 + off);
                v[4 * i + 0] = q.x; v[4 * i + 1] = q.y;
                v[4 * i + 2] = q.z; v[4 * i + 3] = q.w;
            }
        }
        for (int t = 0; t < TV; t++) {
            float vn[16];
            if (t + 1 < TV) {
                const float* vp = g_vin + ((size_t)(t + 1) * B_ + b) * DG;
                #pragma unroll
                for (int i = 0; i < 4; i++) {
                    float4 q = *(const float4*)(vp + i * 128 + off);
                    vn[4 * i + 0] = q.x; vn[4 * i + 1] = q.y;
                    vn[4 * i + 2] = q.z; vn[4 * i + 3] = q.w;
                }
            }
            #pragma unroll
            for (int i = 0; i < 16; i++) g[i] = fmaxf(g[i] + v[i], 0.0f);
            float inv = warp_inv_norm(g);
            #pragma unroll
            for (int i = 0; i < 16; i++) g[i] *= inv;

            float* op = out + ((size_t)b * T_ + (t + 1)) * DG;
            #pragma unroll
            for (int i = 0; i < 4; i++)
                *(float4*)(op + i * 128 + off) =
                    make_float4(g[4 * i], g[4 * i + 1], g[4 * i + 2], g[4 * i + 3]);

            if (t + 1 < TV) {
                #pragma unroll
                for (int i = 0; i < 16; i++) v[i] = vn[i];
            }
        }
    } else {
        // general path: full g @ W_rec^T per step (correct, slow)
        __shared__ float gs[DG];
        for (int t = 0; t < TV; t++) {
            #pragma unroll
            for (int i = 0; i < 4; i++)
                #pragma unroll
                for (int c = 0; c < 4; c++)
                    gs[i * 128 + off + c] = g[4 * i + c];
            __syncwarp();

            const float* vrow = g_vin + ((size_t)t * B_ + b) * DG;
            float y[16];
            #pragma unroll
            for (int i = 0; i < 4; i++) {
                #pragma unroll
                for (int c = 0; c < 4; c++) {
                    int j = i * 128 + off + c;
                    float acc = vrow[j];
                    const float* wrow = Wr + (size_t)j * DG;
                    for (int k = 0; k < DG; k++) acc += gs[k] * wrow[k];
                    y[4 * i + c] = fmaxf(acc, 0.0f);
                }
            }
            float inv = warp_inv_norm(y);
            #pragma unroll
            for (int i = 0; i < 16; i++) g[i] = y[i] * inv;

            float* op = out + ((size_t)b * T_ + (t + 1)) * DG;
            #pragma unroll
            for (int i = 0; i < 4; i++)
                *(float4*)(op + i * 128 + off) =
                    make_float4(g[4 * i], g[4 * i + 1], g[4 * i + 2], g[4 * i + 3]);
            __syncwarp();
        }
    }
}

// ---------------------------------------------------------------------------
extern "C" void kernel_launch(void* const* d_in, const int* in_sizes, int n_in,
                              void* d_out, int out_size) {
    (void)in_sizes; (void)n_in; (void)out_size;
    const float* L   = (const float*)d_in[0];
    const float* W1  = (const float*)d_in[1];
    const float* b1  = (const float*)d_in[2];
    const float* W2  = (const float*)d_in[3];
    const float* b2  = (const float*)d_in[4];
    const float* W3  = (const float*)d_in[5];
    const float* b3  = (const float*)d_in[6];
    const float* Wr  = (const float*)d_in[7];
    const float* Win = (const float*)d_in[8];
    float* out = (float*)d_out;

    reset_flag_k<<<1, 1>>>();
    check_id_k<<<(DG * DG + 255) / 256, 256>>>(Wr);

    prep_w_k<<<(DG * DIN / 4) / 256, 256>>>(Win);

    dim3 vgrid(DG / BN, (MV + BM - 1) / BM);   // (4, 256)
    vin_mma_k<<<vgrid, 256, VIN_SMEM>>>(L);

    // MLP head: split-K (deterministic partials + reduce)
    // stage 0: K=1024, 8 slices of 128; N=1024
    mlp_part_k<<<dim3(DHID / 64, 8), 256>>>(L, T_ * DIN, 0, W1, DHID, 128);
    mlp_red_k<<<(B_ * DHID) / 256, 256>>>(b1, 0, DHID, 8);
    // stage 1: K=1024, 8 slices; N=512
    mlp_part_k<<<dim3(DG / 64, 8), 256>>>(nullptr, DHID, 1, W2, DG, 128);
    mlp_red_k<<<(B_ * DG) / 256, 256>>>(b2, 1, DG, 8);
    // stage 2: K=512, 4 slices; N=512
    mlp_part_k<<<dim3(DG / 64, 4), 256>>>(nullptr, DG, 2, W3, DG, 128);
    mlp_red_k<<<(B_ * DG) / 256, 256>>>(b3, 2, DG, 4);

    scan_k<<<B_, 32>>>(Wr, out);
}